// round 3
// baseline (speedup 1.0000x reference)
#include <cuda_runtime.h>

// Problem constants (fixed by the reference)
#define BB    256
#define TT    2048
#define HID   20
#define EMB   10
#define VOCAB 128

// Scratch (static device globals — no runtime allocation)
__device__ float g_hs[(size_t)BB * TT * HID];   // hidden states, [b][t][j], ~42 MB
__device__ float g_proj[VOCAB * HID];           // per-vocab input contribution incl. both biases

// ---------------------------------------------------------------------------
// Kernel 1: proj[v][j] = b_ih[j] + b_hh[j] + sum_e emb[v][e] * W_ih[j][e]
// ---------------------------------------------------------------------------
__global__ void proj_kernel(const float* __restrict__ emb,
                            const float* __restrict__ W_ih,
                            const float* __restrict__ b_ih,
                            const float* __restrict__ b_hh) {
    int v = blockIdx.x;
    int j = threadIdx.x;
    if (j >= HID) return;
    float acc = b_ih[j] + b_hh[j];
#pragma unroll
    for (int e = 0; e < EMB; ++e)
        acc = fmaf(emb[v * EMB + e], W_ih[j * EMB + e], acc);
    g_proj[v * HID + j] = acc;
}

// ---------------------------------------------------------------------------
// Fast, accurate tanh: 1 - 2/(exp(2x)+1). MUFU.EX2 + MUFU.RCP; rel err ~1e-6.
// Correct saturation at both infinities.
// ---------------------------------------------------------------------------
__device__ __forceinline__ float fast_tanh(float x) {
    float e = __expf(2.0f * x);
    return 1.0f - __fdividef(2.0f, e + 1.0f);
}

// ---------------------------------------------------------------------------
// Kernel 2: the recurrence. One warp per batch row.
// Lane j (< 20) owns h[j] and W_hh row j in registers.
// Per step: broadcast h via SHFL, 4 interleaved FMA chains, fast tanh.
// Input-table lookups are software-pipelined one step ahead (h-independent).
// ---------------------------------------------------------------------------
__global__ void __launch_bounds__(32) rnn_kernel(const int* __restrict__ inputs,
                                                 const float* __restrict__ W_hh) {
    __shared__ float s_proj[VOCAB * HID];
    __shared__ int   s_idx[32];

    const int  b   = blockIdx.x;
    const int  j   = threadIdx.x;
    const bool act = (j < HID);

    // Stage proj table into shared (broadcast reads later, conflict-free)
    for (int i = j; i < VOCAB * HID; i += 32)
        s_proj[i] = g_proj[i];

    // W_hh row in registers (zeros for inactive lanes so their h stays 0)
    float w[HID];
#pragma unroll
    for (int k = 0; k < HID; ++k)
        w[k] = act ? W_hh[j * HID + k] : 0.0f;

    const int* inp = inputs + (size_t)b * TT;
    float*     hs  = g_hs + (size_t)b * TT * HID + j;

    __syncthreads();

    float h = 0.0f;
    for (int tc = 0; tc < TT; tc += 32) {
        s_idx[j] = inp[tc + j];          // coalesced 128B chunk of indices
        __syncwarp();

        float x = act ? s_proj[s_idx[0] * HID + j] : 0.0f;   // prefetch step 0
#pragma unroll
        for (int tt = 0; tt < 32; ++tt) {
            const float xc = x;
            if (tt < 31)                                      // prefetch next step's x
                x = act ? s_proj[s_idx[tt + 1] * HID + j] : 0.0f;

            // z_j = xc + sum_k W_hh[j][k] * h[k]   (4 interleaved chains, depth 5)
            float a0 = 0.f, a1 = 0.f, a2 = 0.f, a3 = 0.f;
#pragma unroll
            for (int k = 0; k < HID; k += 4) {
                a0 = fmaf(w[k + 0], __shfl_sync(0xffffffffu, h, k + 0), a0);
                a1 = fmaf(w[k + 1], __shfl_sync(0xffffffffu, h, k + 1), a1);
                a2 = fmaf(w[k + 2], __shfl_sync(0xffffffffu, h, k + 2), a2);
                a3 = fmaf(w[k + 3], __shfl_sync(0xffffffffu, h, k + 3), a3);
            }
            h = fast_tanh(xc + ((a0 + a1) + (a2 + a3)));

            if (act) hs[(size_t)(tc + tt) * HID] = h;         // fire-and-forget
        }
        __syncwarp();
    }
}

// ---------------------------------------------------------------------------
// Kernel 3: out[bt][v] = hs[bt][:] . W_out[v][:] + b_out[v]
// Block tile: 64 bt x 128 v; thread tile: 4 bt x 8 v (32 accumulators).
// ---------------------------------------------------------------------------
__global__ void __launch_bounds__(256) out_kernel(const float* __restrict__ W_out,
                                                  const float* __restrict__ b_out,
                                                  float* __restrict__ out) {
    __shared__ float s_h[HID][64];      // transposed: [k][bt_local]
    __shared__ float s_w[HID][VOCAB];   // transposed: [k][v]
    __shared__ float s_b[VOCAB];

    const int    tid = threadIdx.x;
    const size_t bt0 = (size_t)blockIdx.x * 64;

    for (int i = tid; i < VOCAB * HID; i += 256) {
        int v = i / HID, k = i - v * HID;
        s_w[k][v] = W_out[i];
    }
    if (tid < VOCAB) s_b[tid] = b_out[tid];

    const float* hsrc = g_hs + bt0 * HID;
    for (int i = tid; i < 64 * HID; i += 256) {
        int m = i / HID, k = i - m * HID;
        s_h[k][m] = hsrc[i];
    }
    __syncthreads();

    const int vg = (tid & 15) * 8;      // 16 v-groups of 8  -> 128 v
    const int bg = (tid >> 4) * 4;      // 16 bt-groups of 4 -> 64 bt

    float acc[4][8];
#pragma unroll
    for (int m = 0; m < 4; ++m)
#pragma unroll
        for (int n = 0; n < 8; ++n)
            acc[m][n] = s_b[vg + n];

#pragma unroll
    for (int k = 0; k < HID; ++k) {
        float hv[4], wv[8];
#pragma unroll
        for (int m = 0; m < 4; ++m) hv[m] = s_h[k][bg + m];
#pragma unroll
        for (int n = 0; n < 8; ++n) wv[n] = s_w[k][vg + n];
#pragma unroll
        for (int m = 0; m < 4; ++m)
#pragma unroll
            for (int n = 0; n < 8; ++n)
                acc[m][n] = fmaf(hv[m], wv[n], acc[m][n]);
    }

#pragma unroll
    for (int m = 0; m < 4; ++m) {
        float4* dst = reinterpret_cast<float4*>(out + (bt0 + bg + m) * VOCAB + vg);
        dst[0] = make_float4(acc[m][0], acc[m][1], acc[m][2], acc[m][3]);
        dst[1] = make_float4(acc[m][4], acc[m][5], acc[m][6], acc[m][7]);
    }
}

// ---------------------------------------------------------------------------
// Launch. Inputs in metadata order:
// 0: inputs int32 [B,T]   1: emb [128,10]   2: W_ih [20,10]   3: W_hh [20,20]
// 4: b_ih [20]            5: b_hh [20]      6: W_out [128,20] 7: b_out [128]
// Output: float32 [B,T,VOCAB]
// ---------------------------------------------------------------------------
extern "C" void kernel_launch(void* const* d_in, const int* in_sizes, int n_in,
                              void* d_out, int out_size) {
    const int*   inputs = (const int*)d_in[0];
    const float* emb    = (const float*)d_in[1];
    const float* W_ih   = (const float*)d_in[2];
    const float* W_hh   = (const float*)d_in[3];
    const float* b_ih   = (const float*)d_in[4];
    const float* b_hh   = (const float*)d_in[5];
    const float* W_out  = (const float*)d_in[6];
    const float* b_out  = (const float*)d_in[7];
    float*       out    = (float*)d_out;

    proj_kernel<<<VOCAB, 32>>>(emb, W_ih, b_ih, b_hh);
    rnn_kernel<<<BB, 32>>>(inputs, W_hh);
    out_kernel<<<(BB * TT) / 64, 256>>>(W_out, b_out, out);
}

// round 4
// speedup vs baseline: 1.1009x; 1.1009x over previous
#include <cuda_runtime.h>

// Fixed problem shape
#define BB    256
#define TT    2048
#define HID   20
#define EMB   10
#define VOCAB 128

#define RING  256            // h ring slots (power of 2), 20 floats each
#define TILE  32             // timesteps per publish/consume tile
#define NTILES (TT / TILE)   // 64
#define NCONS 7              // warps 0..6 consume; warp 7 produces

typedef unsigned long long ull;

// ---- packed f32x2 helpers (FFMA2 — only reachable via PTX) --------------
__device__ __forceinline__ ull pk(float lo, float hi) {
    ull r; asm("mov.b64 %0, {%1,%2};" : "=l"(r) : "f"(lo), "f"(hi)); return r;
}
__device__ __forceinline__ void upk(float& lo, float& hi, ull v) {
    asm("mov.b64 {%0,%1}, %2;" : "=f"(lo), "=f"(hi) : "l"(v));
}
__device__ __forceinline__ void dfma(ull& d, ull a, ull b) {
    asm("fma.rn.f32x2 %0, %1, %2, %0;" : "+l"(d) : "l"(a), "l"(b));
}
__device__ __forceinline__ ull dadd(ull a, ull b) {
    ull r; asm("add.rn.f32x2 %0, %1, %2;" : "=l"(r) : "l"(a), "l"(b)); return r;
}

// Accurate fast tanh: 1 - 2/(exp(2x)+1); MUFU.EX2 + MUFU.RCP, rel err ~1e-6
__device__ __forceinline__ float fast_tanh(float x) {
    float e = __expf(x + x);
    return 1.0f - __fdividef(2.0f, e + 1.0f);
}

// ---------------------------------------------------------------------------
// One block per batch row. Warp 7 (producer): the recurrence, h published to a
// shared ring. Warps 0-6 (consumers): project finished timesteps to vocab.
// ---------------------------------------------------------------------------
__global__ void __launch_bounds__(256, 2) fused_rnn_kernel(
    const int*   __restrict__ inputs,
    const float* __restrict__ emb,
    const float* __restrict__ W_ih,
    const float* __restrict__ W_hh,
    const float* __restrict__ b_ih,
    const float* __restrict__ b_hh,
    const float* __restrict__ W_out,
    const float* __restrict__ b_out,
    float*       __restrict__ out)
{
    __shared__ __align__(16) float s_proj[VOCAB * HID];   // 10 KB
    __shared__ __align__(16) float s_ring[RING * HID];    // 20 KB
    __shared__ volatile int s_prog;                       // steps produced
    __shared__ volatile int s_done[NCONS];                // steps consumed / warp

    const int tid  = threadIdx.x;
    const int lane = tid & 31;
    const int wid  = tid >> 5;
    const int b    = blockIdx.x;

    // proj[v][j] = b_ih[j]+b_hh[j] + sum_e emb[v][e]*W_ih[j][e]  (all threads)
    for (int i = tid; i < VOCAB * HID; i += 256) {
        int v = i / HID, j = i - v * HID;
        float acc = b_ih[j] + b_hh[j];
#pragma unroll
        for (int e = 0; e < EMB; ++e)
            acc = fmaf(emb[v * EMB + e], W_ih[j * EMB + e], acc);
        s_proj[i] = acc;
    }
    if (tid == 0) s_prog = 0;
    if (tid < NCONS) s_done[tid] = 0;
    if (tid < HID) s_ring[(RING - 1) * HID + tid] = 0.0f;   // h_{-1} = 0
    __syncthreads();

    if (wid == NCONS) {
        // ================= PRODUCER (warp 7: highest wid = arbiter priority)
        const int  j   = lane;
        const bool act = (j < HID);

        ull w[10];
        if (act) {
            const float4* wr = (const float4*)(W_hh + j * HID);  // 80B aligned
#pragma unroll
            for (int q = 0; q < 5; ++q) {
                float4 f = wr[q];
                w[2*q]   = pk(f.x, f.y);
                w[2*q+1] = pk(f.z, f.w);
            }
        } else {
#pragma unroll
            for (int q = 0; q < 10; ++q) w[q] = 0ull;
        }

        const int* inp = inputs + (size_t)b * TT;
        int myidx = inp[lane];   // 32 indices of first chunk

        for (int tc = 0; tc < TT; tc += TILE) {
            // prefetch next chunk's indices (off critical path)
            int nextidx = (tc + TILE < TT) ? inp[tc + TILE + lane] : 0;

            // back-pressure: don't overwrite ring slots consumers still need
            int need = tc + TILE - RING;
            if (need > 0) {
                if (lane == 0) {
                    for (;;) {
                        int m = s_done[0];
#pragma unroll
                        for (int k = 1; k < NCONS; ++k) m = min(m, s_done[k]);
                        if (m >= need) break;
                        __nanosleep(128);
                    }
                }
                __syncwarp();
            }

            int vi = __shfl_sync(0xffffffffu, myidx, 0);
            float x = act ? s_proj[vi * HID + j] : 0.0f;

#pragma unroll
            for (int tt = 0; tt < TILE; ++tt) {
                const int t = tc + tt;
                const float xc = x;
                if (tt < TILE - 1) {                       // prefetch next x
                    int v2 = __shfl_sync(0xffffffffu, myidx, tt + 1);
                    x = act ? s_proj[v2 * HID + j] : 0.0f;
                }

                // broadcast h_{t-1} from ring: 5 x LDS.128 (conflict-free)
                const ulonglong2* hp = (const ulonglong2*)
                    (s_ring + ((t + RING - 1) & (RING - 1)) * HID);
                ulonglong2 p0 = hp[0], p1 = hp[1], p2 = hp[2], p3 = hp[3], p4 = hp[4];

                // z_j = xc + W_hh[j,:].h : 2 interleaved packed-FMA chains
                ull c0 = pk(xc, 0.0f);
                ull c1 = pk(0.0f, 0.0f);
                dfma(c0, w[0], p0.x); dfma(c1, w[1], p0.y);
                dfma(c0, w[2], p1.x); dfma(c1, w[3], p1.y);
                dfma(c0, w[4], p2.x); dfma(c1, w[5], p2.y);
                dfma(c0, w[6], p3.x); dfma(c1, w[7], p3.y);
                dfma(c0, w[8], p4.x); dfma(c1, w[9], p4.y);
                float lo, hi; upk(lo, hi, dadd(c0, c1));

                float hnew = fast_tanh(lo + hi);
                if (act) s_ring[(t & (RING - 1)) * HID + j] = hnew;
                __syncwarp();    // make h_t visible for next step's LDS
            }
            myidx = nextidx;

            // publish chunk to consumers
            __threadfence_block();
            __syncwarp();
            if (lane == 0) s_prog = tc + TILE;
        }
    } else {
        // ================= CONSUMERS (warps 0-6): out[t][v] = h_t . W_out[v] + b
        const int v0 = lane * 4;          // 32 lanes x 4 vocab = 128
        ull   wo[4][10];
        ull   bo[4];
#pragma unroll
        for (int r = 0; r < 4; ++r) {
            const float4* wr = (const float4*)(W_out + (v0 + r) * HID);
#pragma unroll
            for (int q = 0; q < 5; ++q) {
                float4 f = wr[q];
                wo[r][2*q]   = pk(f.x, f.y);
                wo[r][2*q+1] = pk(f.z, f.w);
            }
            bo[r] = pk(b_out[v0 + r], 0.0f);
        }

        for (int tl = wid; tl < NTILES; tl += NCONS) {
            const int t0   = tl * TILE;
            const int tend = t0 + TILE;
            if (lane == 0) {
                while (s_prog < tend) __nanosleep(128);
            }
            __syncwarp();
            __threadfence_block();

            float* outp = out + ((size_t)b * TT + t0) * VOCAB + v0;
#pragma unroll 4
            for (int tt = 0; tt < TILE; ++tt) {
                const ulonglong2* hp = (const ulonglong2*)
                    (s_ring + ((t0 + tt) & (RING - 1)) * HID);
                ulonglong2 p0 = hp[0], p1 = hp[1], p2 = hp[2], p3 = hp[3], p4 = hp[4];
                ull hv0 = p0.x, hv1 = p0.y, hv2 = p1.x, hv3 = p1.y, hv4 = p2.x;
                ull hv5 = p2.y, hv6 = p3.x, hv7 = p3.y, hv8 = p4.x, hv9 = p4.y;

                float4 res;
#pragma unroll
                for (int r = 0; r < 4; ++r) {
                    ull acc = bo[r];
                    dfma(acc, wo[r][0], hv0); dfma(acc, wo[r][1], hv1);
                    dfma(acc, wo[r][2], hv2); dfma(acc, wo[r][3], hv3);
                    dfma(acc, wo[r][4], hv4); dfma(acc, wo[r][5], hv5);
                    dfma(acc, wo[r][6], hv6); dfma(acc, wo[r][7], hv7);
                    dfma(acc, wo[r][8], hv8); dfma(acc, wo[r][9], hv9);
                    float lo, hi; upk(lo, hi, acc);
                    (&res.x)[r] = lo + hi;
                }
                *(float4*)(outp + (size_t)tt * VOCAB) = res;   // 512B coalesced
            }
            __syncwarp();
            if (lane == 0) s_done[wid] = tend;
        }
    }
}

// ---------------------------------------------------------------------------
// Inputs (metadata order):
// 0: inputs int32 [256,2048]  1: emb [128,10]  2: W_ih [20,10]  3: W_hh [20,20]
// 4: b_ih [20]  5: b_hh [20]  6: W_out [128,20]  7: b_out [128]
// Output: float32 [256,2048,128]
// ---------------------------------------------------------------------------
extern "C" void kernel_launch(void* const* d_in, const int* in_sizes, int n_in,
                              void* d_out, int out_size) {
    const int*   inputs = (const int*)d_in[0];
    const float* emb    = (const float*)d_in[1];
    const float* W_ih   = (const float*)d_in[2];
    const float* W_hh   = (const float*)d_in[3];
    const float* b_ih   = (const float*)d_in[4];
    const float* b_hh   = (const float*)d_in[5];
    const float* W_out  = (const float*)d_in[6];
    const float* b_out  = (const float*)d_in[7];
    float*       out    = (float*)d_out;

    fused_rnn_kernel<<<BB, 256>>>(inputs, emb, W_ih, W_hh, b_ih, b_hh,
                                  W_out, b_out, out);
}

// round 5
// speedup vs baseline: 1.2155x; 1.1041x over previous
#include <cuda_runtime.h>

// Fixed problem shape
#define BB    256
#define TT    2048
#define HID   20
#define EMB   10
#define VOCAB 128

#define RING  256            // h ring slots (power of 2), 20 floats each
#define TILE  32             // timesteps per publish/consume tile
#define NTILES (TT / TILE)   // 64
#define NCONS 7              // warps 0..6 consume; warp 7 produces

typedef unsigned long long ull;

// ---- packed f32x2 helpers (FFMA2 — only reachable via PTX) --------------
__device__ __forceinline__ ull pk(float lo, float hi) {
    ull r; asm("mov.b64 %0, {%1,%2};" : "=l"(r) : "f"(lo), "f"(hi)); return r;
}
__device__ __forceinline__ void upk(float& lo, float& hi, ull v) {
    asm("mov.b64 {%0,%1}, %2;" : "=f"(lo), "=f"(hi) : "l"(v));
}
__device__ __forceinline__ void dfma(ull& d, ull a, ull b) {
    asm("fma.rn.f32x2 %0, %1, %2, %0;" : "+l"(d) : "l"(a), "l"(b));
}
__device__ __forceinline__ ull dadd(ull a, ull b) {
    ull r; asm("add.rn.f32x2 %0, %1, %2;" : "=l"(r) : "l"(a), "l"(b)); return r;
}

// Minimal-chain accurate tanh: (e-1)/(e+1), e = 2^(z * 2/ln2).
// FMUL(4) + EX2(16) + FADD||FADD(4) + RCP(16) + FMUL(4) ~= 44 cyc chain.
__device__ __forceinline__ float fast_tanh(float z) {
    float e, r;
    asm("ex2.approx.f32 %0, %1;" : "=f"(e) : "f"(z * 2.885390081777927f));
    asm("rcp.approx.f32 %0, %1;" : "=f"(r) : "f"(e + 1.0f));
    return (e - 1.0f) * r;
}

// ---------------------------------------------------------------------------
// One block per batch row. Warp 7 (producer): the recurrence; h lives in the
// smem ring only (scalar-owner lanes, STS -> in-order LSU -> LDS next step,
// NO per-step syncwarp, NO shuffles). Warps 0-6 (consumers): vocab projection.
// ---------------------------------------------------------------------------
__global__ void __launch_bounds__(256, 2) fused_rnn_kernel(
    const int*   __restrict__ inputs,
    const float* __restrict__ emb,
    const float* __restrict__ W_ih,
    const float* __restrict__ W_hh,
    const float* __restrict__ b_ih,
    const float* __restrict__ b_hh,
    const float* __restrict__ W_out,
    const float* __restrict__ b_out,
    float*       __restrict__ out)
{
    __shared__ __align__(16) float s_proj[VOCAB * HID];   // 10 KB
    __shared__ __align__(16) float s_ring[RING * HID];    // 20 KB
    __shared__ int s_idx[TILE];
    __shared__ volatile int s_prog;                       // steps produced
    __shared__ volatile int s_done[NCONS];                // steps consumed / warp

    const int tid  = threadIdx.x;
    const int lane = tid & 31;
    const int wid  = tid >> 5;
    const int b    = blockIdx.x;

    // proj[v][j] = b_ih[j]+b_hh[j] + sum_e emb[v][e]*W_ih[j][e]  (all threads)
    for (int i = tid; i < VOCAB * HID; i += 256) {
        int v = i / HID, j = i - v * HID;
        float acc = b_ih[j] + b_hh[j];
#pragma unroll
        for (int e = 0; e < EMB; ++e)
            acc = fmaf(emb[v * EMB + e], W_ih[j * EMB + e], acc);
        s_proj[i] = acc;
    }
    if (tid == 0) s_prog = 0;
    if (tid < NCONS) s_done[tid] = 0;
    if (tid < HID) s_ring[(RING - 1) * HID + tid] = 0.0f;   // h_{-1} = 0
    __syncthreads();

    if (wid == NCONS) {
        // ================= PRODUCER (warp 7: highest wid = arbiter priority)
        const int  j   = lane;
        const bool act = (j < HID);
        const int  jx  = act ? j : 0;          // clamped lane for x loads

        ull w2[10];
        if (act) {
            const float4* wr = (const float4*)(W_hh + j * HID);  // 80B-aligned
#pragma unroll
            for (int q = 0; q < 5; ++q) {
                float4 f = wr[q];
                w2[2*q]   = pk(f.x, f.y);
                w2[2*q+1] = pk(f.z, f.w);
            }
        } else {
#pragma unroll
            for (int q = 0; q < 10; ++q) w2[q] = 0ull;
        }

        const int* inp = inputs + (size_t)b * TT;

        // prologue: stage chunk-0 indices, prefetch x_0
        s_idx[lane] = inp[lane];
        __syncwarp();
        float x = s_proj[s_idx[0] * HID + jx];

        for (int tc = 0; tc < TT; tc += TILE) {
            // prefetch next chunk's indices into regs (off critical path)
            int nextidx = (tc + TILE < TT) ? inp[tc + TILE + lane] : 0;

            // back-pressure: don't overwrite ring slots consumers still need
            int need = tc + TILE - RING;
            if (need > 0) {
                if (lane == 0) {
                    for (;;) {
                        int m = s_done[0];
#pragma unroll
                        for (int k = 1; k < NCONS; ++k) m = min(m, s_done[k]);
                        if (m >= need) break;
                        __nanosleep(128);
                    }
                }
                __syncwarp();
            }

#pragma unroll
            for (int tt = 0; tt < TILE; ++tt) {
                const int t = tc + tt;

                // broadcast h_{t-1} from ring: 5 x LDS.128, uniform address
                const ulonglong2* hp = (const ulonglong2*)
                    (s_ring + ((t + RING - 1) & (RING - 1)) * HID);
                ulonglong2 p0 = hp[0], p1 = hp[1], p2 = hp[2], p3 = hp[3], p4 = hp[4];

                // z_j = x + W_hh[j,:].h : two interleaved packed-FMA chains
                ull c0 = pk(x, 0.0f);
                ull c1 = pk(0.0f, 0.0f);
                dfma(c0, w2[0], p0.x); dfma(c1, w2[1], p0.y);
                dfma(c0, w2[2], p1.x); dfma(c1, w2[3], p1.y);
                dfma(c0, w2[4], p2.x); dfma(c1, w2[5], p2.y);
                dfma(c0, w2[6], p3.x); dfma(c1, w2[7], p3.y);
                dfma(c0, w2[8], p4.x); dfma(c1, w2[9], p4.y);
                float lo, hi; upk(lo, hi, dadd(c0, c1));

                // prefetch next step's x (independent of h chain)
                if (tt < TILE - 1)
                    x = s_proj[s_idx[tt + 1] * HID + jx];

                float hn = fast_tanh(lo + hi);
                if (act) s_ring[(t & (RING - 1)) * HID + j] = hn;
                // NOTE: no __syncwarp — same-warp STS->LDS is LSU-ordered
            }

            // publish chunk; stage next chunk's indices
            __syncwarp();                       // cross-lane STS completion
            __threadfence_block();
            if (lane == 0) s_prog = tc + TILE;
            s_idx[lane] = nextidx;
            __syncwarp();
            x = s_proj[s_idx[0] * HID + jx];    // first x of next chunk
        }
    } else {
        // ================= CONSUMERS (warps 0-6): out[t][v] = h_t . W_out[v] + b
        const int v0 = lane * 4;          // 32 lanes x 4 vocab = 128
        ull   wo[4][10];
        ull   bo[4];
#pragma unroll
        for (int r = 0; r < 4; ++r) {
            const float4* wr = (const float4*)(W_out + (v0 + r) * HID);
#pragma unroll
            for (int q = 0; q < 5; ++q) {
                float4 f = wr[q];
                wo[r][2*q]   = pk(f.x, f.y);
                wo[r][2*q+1] = pk(f.z, f.w);
            }
            bo[r] = pk(b_out[v0 + r], 0.0f);
        }

        for (int tl = wid; tl < NTILES; tl += NCONS) {
            const int t0   = tl * TILE;
            const int tend = t0 + TILE;
            if (lane == 0) {
                while (s_prog < tend) __nanosleep(128);
            }
            __syncwarp();
            __threadfence_block();

            float* outp = out + ((size_t)b * TT + t0) * VOCAB + v0;
#pragma unroll 4
            for (int tt = 0; tt < TILE; ++tt) {
                const ulonglong2* hp = (const ulonglong2*)
                    (s_ring + ((t0 + tt) & (RING - 1)) * HID);
                ulonglong2 p0 = hp[0], p1 = hp[1], p2 = hp[2], p3 = hp[3], p4 = hp[4];

                float4 res;
#pragma unroll
                for (int r = 0; r < 4; ++r) {
                    ull acc = bo[r];
                    dfma(acc, wo[r][0], p0.x); dfma(acc, wo[r][1], p0.y);
                    dfma(acc, wo[r][2], p1.x); dfma(acc, wo[r][3], p1.y);
                    dfma(acc, wo[r][4], p2.x); dfma(acc, wo[r][5], p2.y);
                    dfma(acc, wo[r][6], p3.x); dfma(acc, wo[r][7], p3.y);
                    dfma(acc, wo[r][8], p4.x); dfma(acc, wo[r][9], p4.y);
                    float lo, hi; upk(lo, hi, acc);
                    (&res.x)[r] = lo + hi;
                }
                *(float4*)(outp + (size_t)tt * VOCAB) = res;   // 512B coalesced
            }
            __syncwarp();
            if (lane == 0) s_done[wid] = tend;
        }
    }
}

// ---------------------------------------------------------------------------
// Inputs (metadata order):
// 0: inputs int32 [256,2048]  1: emb [128,10]  2: W_ih [20,10]  3: W_hh [20,20]
// 4: b_ih [20]  5: b_hh [20]  6: W_out [128,20]  7: b_out [128]
// Output: float32 [256,2048,128]
// ---------------------------------------------------------------------------
extern "C" void kernel_launch(void* const* d_in, const int* in_sizes, int n_in,
                              void* d_out, int out_size) {
    const int*   inputs = (const int*)d_in[0];
    const float* emb    = (const float*)d_in[1];
    const float* W_ih   = (const float*)d_in[2];
    const float* W_hh   = (const float*)d_in[3];
    const float* b_ih   = (const float*)d_in[4];
    const float* b_hh   = (const float*)d_in[5];
    const float* W_out  = (const float*)d_in[6];
    const float* b_out  = (const float*)d_in[7];
    float*       out    = (float*)d_out;

    fused_rnn_kernel<<<BB, 256>>>(inputs, emb, W_ih, W_hh, b_ih, b_hh,
                                  W_out, b_out, out);
}

// round 6
// speedup vs baseline: 1.2442x; 1.0236x over previous
#include <cuda_runtime.h>

// Fixed problem shape
#define BB    256
#define TT    2048
#define HID   20
#define EMB   10
#define VOCAB 128

#define RING  128            // h ring slots (power of 2), 20 floats each
#define TILE  32             // timesteps per publish/consume tile
#define NTILES (TT / TILE)   // 64
#define NCONS 3              // warps 0..2 consume; warp 3 produces

// 2/ln(2): folded into W_hh and proj so tanh needs no pre-multiply
#define EXSCALE 2.885390081777926815f

typedef unsigned long long ull;

// ---- packed f32x2 helpers (FFMA2 — only reachable via PTX) --------------
__device__ __forceinline__ ull pk(float lo, float hi) {
    ull r; asm("mov.b64 %0, {%1,%2};" : "=l"(r) : "f"(lo), "f"(hi)); return r;
}
__device__ __forceinline__ void upk(float& lo, float& hi, ull v) {
    asm("mov.b64 {%0,%1}, %2;" : "=f"(lo), "=f"(hi) : "l"(v));
}
__device__ __forceinline__ void dfma(ull& d, ull a, ull b) {
    asm("fma.rn.f32x2 %0, %1, %2, %0;" : "+l"(d) : "l"(a), "l"(b));
}
__device__ __forceinline__ ull dadd(ull a, ull b) {
    ull r; asm("add.rn.f32x2 %0, %1, %2;" : "=l"(r) : "l"(a), "l"(b)); return r;
}

// tanh with pre-scaled argument: input z' = (2/ln2) * z.
// e = 2^z'; tanh = (e-1)*rcp(e+1).  EX2(16) + FADD(4) + RCP(16) + FMUL(4) = 40.
__device__ __forceinline__ float tanh_prescaled(float zs) {
    float e, r;
    asm("ex2.approx.f32 %0, %1;" : "=f"(e) : "f"(zs));
    asm("rcp.approx.f32 %0, %1;" : "=f"(r) : "f"(e + 1.0f));
    return (e - 1.0f) * r;
}

// ---------------------------------------------------------------------------
// One block per batch row, 128 threads.
// Warp 3 (producer, own SMSP): the recurrence; h published to a smem ring.
// Warps 0-2 (consumers): project finished 32-step tiles to the 128-vocab out.
// ---------------------------------------------------------------------------
__global__ void __launch_bounds__(128, 2) fused_rnn_kernel(
    const int*   __restrict__ inputs,
    const float* __restrict__ emb,
    const float* __restrict__ W_ih,
    const float* __restrict__ W_hh,
    const float* __restrict__ b_ih,
    const float* __restrict__ b_hh,
    const float* __restrict__ W_out,
    const float* __restrict__ b_out,
    float*       __restrict__ out)
{
    __shared__ __align__(16) float s_proj[VOCAB * HID];   // 10 KB (pre-scaled)
    __shared__ __align__(16) float s_ring[RING * HID];    // 10 KB
    __shared__ int s_idx[TILE];
    __shared__ volatile int s_prog;                       // steps produced
    __shared__ volatile int s_done[NCONS];                // steps consumed / warp

    const int tid  = threadIdx.x;
    const int lane = tid & 31;
    const int wid  = tid >> 5;
    const int b    = blockIdx.x;

    // proj[v][j] = EXSCALE * (b_ih[j]+b_hh[j] + sum_e emb[v][e]*W_ih[j][e])
    for (int i = tid; i < VOCAB * HID; i += 128) {
        int v = i / HID, j = i - v * HID;
        float acc = b_ih[j] + b_hh[j];
#pragma unroll
        for (int e = 0; e < EMB; ++e)
            acc = fmaf(emb[v * EMB + e], W_ih[j * EMB + e], acc);
        s_proj[i] = acc * EXSCALE;
    }
    if (tid == 0) s_prog = 0;
    if (tid < NCONS) s_done[tid] = 0;
    if (tid < HID) s_ring[(RING - 1) * HID + tid] = 0.0f;   // h_{-1} = 0
    __syncthreads();

    if (wid == NCONS) {
        // ================= PRODUCER (warp 3, alone on SMSP 3 of this block)
        const int  j   = lane;
        const bool act = (j < HID);
        const int  jx  = act ? j : 0;          // clamped lane for x loads

        // W_hh row, pre-scaled by EXSCALE, packed f32x2
        ull w2[10];
        if (act) {
            const float4* wr = (const float4*)(W_hh + j * HID);  // 80B-aligned
#pragma unroll
            for (int q = 0; q < 5; ++q) {
                float4 f = wr[q];
                w2[2*q]   = pk(f.x * EXSCALE, f.y * EXSCALE);
                w2[2*q+1] = pk(f.z * EXSCALE, f.w * EXSCALE);
            }
        } else {
#pragma unroll
            for (int q = 0; q < 10; ++q) w2[q] = 0ull;
        }

        const int* inp = inputs + (size_t)b * TT;

        // prologue: stage chunk-0 indices, prefetch x_0 (already scaled)
        s_idx[lane] = inp[lane];
        __syncwarp();
        float x = s_proj[s_idx[0] * HID + jx];

        for (int tc = 0; tc < TT; tc += TILE) {
            int nextidx = (tc + TILE < TT) ? inp[tc + TILE + lane] : 0;

            // back-pressure: don't overwrite ring slots consumers still need
            int need = tc + TILE - RING;
            if (need > 0) {
                if (lane == 0) {
                    for (;;) {
                        int m = s_done[0];
#pragma unroll
                        for (int k = 1; k < NCONS; ++k) m = min(m, s_done[k]);
                        if (m >= need) break;
                        __nanosleep(128);
                    }
                }
                __syncwarp();
            }

#pragma unroll
            for (int tt = 0; tt < TILE; ++tt) {
                const int t = tc + tt;

                // broadcast h_{t-1} from ring: 5 x LDS.128, uniform address
                const ulonglong2* hp = (const ulonglong2*)
                    (s_ring + ((t + RING - 1) & (RING - 1)) * HID);
                ulonglong2 p0 = hp[0], p1 = hp[1], p2 = hp[2], p3 = hp[3], p4 = hp[4];

                // z'_j = x + EXSCALE*W_hh[j,:].h : 4 interleaved FFMA2 chains
                ull c0 = pk(x, 0.0f);
                ull c1 = pk(0.0f, 0.0f);
                ull c2 = pk(0.0f, 0.0f);
                ull c3 = pk(0.0f, 0.0f);
                dfma(c0, w2[0], p0.x); dfma(c1, w2[1], p0.y);
                dfma(c2, w2[2], p1.x); dfma(c3, w2[3], p1.y);
                dfma(c0, w2[4], p2.x); dfma(c1, w2[5], p2.y);
                dfma(c2, w2[6], p3.x); dfma(c3, w2[7], p3.y);
                dfma(c0, w2[8], p4.x); dfma(c1, w2[9], p4.y);
                ull d0 = dadd(c0, c1);
                ull d1 = dadd(c2, c3);
                ull d  = dadd(d0, d1);
                float lo, hi; upk(lo, hi, d);

                // prefetch next step's x (independent of h chain)
                if (tt < TILE - 1)
                    x = s_proj[s_idx[tt + 1] * HID + jx];

                float hn = tanh_prescaled(lo + hi);
                if (act) s_ring[(t & (RING - 1)) * HID + j] = hn;
                // no per-step __syncwarp: same-warp STS->LDS is LSU-ordered
            }

            // publish chunk; stage next chunk's indices
            __syncwarp();
            __threadfence_block();
            if (lane == 0) s_prog = tc + TILE;
            s_idx[lane] = nextidx;
            __syncwarp();
            x = s_proj[s_idx[0] * HID + jx];    // first x of next chunk
        }
    } else {
        // ================= CONSUMERS (warps 0-2): out[t][v] = h_t . W_out[v] + b
        const int v0 = lane * 4;          // 32 lanes x 4 vocab = 128
        ull   wo[4][10];
        ull   bo[4];
#pragma unroll
        for (int r = 0; r < 4; ++r) {
            const float4* wr = (const float4*)(W_out + (v0 + r) * HID);
#pragma unroll
            for (int q = 0; q < 5; ++q) {
                float4 f = wr[q];
                wo[r][2*q]   = pk(f.x, f.y);
                wo[r][2*q+1] = pk(f.z, f.w);
            }
            bo[r] = pk(b_out[v0 + r], 0.0f);
        }

        for (int tl = wid; tl < NTILES; tl += NCONS) {
            const int t0   = tl * TILE;
            const int tend = t0 + TILE;
            if (lane == 0) {
                while (s_prog < tend) __nanosleep(128);
            }
            __syncwarp();
            __threadfence_block();

            float* outp = out + ((size_t)b * TT + t0) * VOCAB + v0;
#pragma unroll 4
            for (int tt = 0; tt < TILE; ++tt) {
                const ulonglong2* hp = (const ulonglong2*)
                    (s_ring + ((t0 + tt) & (RING - 1)) * HID);
                ulonglong2 p0 = hp[0], p1 = hp[1], p2 = hp[2], p3 = hp[3], p4 = hp[4];

                float4 res;
#pragma unroll
                for (int r = 0; r < 4; ++r) {
                    ull acc = bo[r];
                    dfma(acc, wo[r][0], p0.x); dfma(acc, wo[r][1], p0.y);
                    dfma(acc, wo[r][2], p1.x); dfma(acc, wo[r][3], p1.y);
                    dfma(acc, wo[r][4], p2.x); dfma(acc, wo[r][5], p2.y);
                    dfma(acc, wo[r][6], p3.x); dfma(acc, wo[r][7], p3.y);
                    dfma(acc, wo[r][8], p4.x); dfma(acc, wo[r][9], p4.y);
                    float lo, hi; upk(lo, hi, acc);
                    (&res.x)[r] = lo + hi;
                }
                *(float4*)(outp + (size_t)tt * VOCAB) = res;   // 512B coalesced
            }
            __syncwarp();
            if (lane == 0) s_done[wid] = tend;
        }
    }
}

// ---------------------------------------------------------------------------
// Inputs (metadata order):
// 0: inputs int32 [256,2048]  1: emb [128,10]  2: W_ih [20,10]  3: W_hh [20,20]
// 4: b_ih [20]  5: b_hh [20]  6: W_out [128,20]  7: b_out [128]
// Output: float32 [256,2048,128]
// ---------------------------------------------------------------------------
extern "C" void kernel_launch(void* const* d_in, const int* in_sizes, int n_in,
                              void* d_out, int out_size) {
    const int*   inputs = (const int*)d_in[0];
    const float* emb    = (const float*)d_in[1];
    const float* W_ih   = (const float*)d_in[2];
    const float* W_hh   = (const float*)d_in[3];
    const float* b_ih   = (const float*)d_in[4];
    const float* b_hh   = (const float*)d_in[5];
    const float* W_out  = (const float*)d_in[6];
    const float* b_out  = (const float*)d_in[7];
    float*       out    = (float*)d_out;

    fused_rnn_kernel<<<BB, 128>>>(inputs, emb, W_ih, W_hh, b_ih, b_hh,
                                  W_out, b_out, out);
}

// round 7
// speedup vs baseline: 1.6761x; 1.3471x over previous
#include <cuda_runtime.h>

// Fixed problem shape
#define BB    256
#define TT    2048
#define HID   20
#define EMB   10
#define VOCAB 128

#define NROW  2              // batch rows per block (interleaved in producer)
#define RING  128            // ring slots per row (power of 2)
#define TILE  32             // timesteps per publish/consume tile
#define NTILES (TT / TILE)   // 64 per row -> 128 consumer tiles per block
#define NCONS 3              // warps 0..2 consume; warp 3 produces

// 2/ln(2): folded into W_hh and proj so tanh needs no pre-multiply
#define EXSCALE 2.885390081777926815f

typedef unsigned long long ull;

// ---- packed f32x2 helpers (FFMA2 — only reachable via PTX) --------------
__device__ __forceinline__ ull pk(float lo, float hi) {
    ull r; asm("mov.b64 %0, {%1,%2};" : "=l"(r) : "f"(lo), "f"(hi)); return r;
}
__device__ __forceinline__ void upk(float& lo, float& hi, ull v) {
    asm("mov.b64 {%0,%1}, %2;" : "=f"(lo), "=f"(hi) : "l"(v));
}
__device__ __forceinline__ void dfma(ull& d, ull a, ull b) {
    asm("fma.rn.f32x2 %0, %1, %2, %0;" : "+l"(d) : "l"(a), "l"(b));
}
__device__ __forceinline__ ull dadd(ull a, ull b) {
    ull r; asm("add.rn.f32x2 %0, %1, %2;" : "=l"(r) : "l"(a), "l"(b)); return r;
}

// tanh with pre-scaled argument: z' = (2/ln2) z; e = 2^z'; tanh = (e-1)*rcp(e+1)
__device__ __forceinline__ float tanh_prescaled(float zs) {
    float e, r;
    asm("ex2.approx.f32 %0, %1;" : "=f"(e) : "f"(zs));
    asm("rcp.approx.f32 %0, %1;" : "=f"(r) : "f"(e + 1.0f));
    return (e - 1.0f) * r;
}

// ---------------------------------------------------------------------------
// One block per TWO batch rows, 128 threads.
// Warp 3 (producer): two interleaved recurrences -> two smem rings.
// Warps 0-2 (consumers): project finished 32-step tiles (both rows) to vocab.
// ---------------------------------------------------------------------------
__global__ void __launch_bounds__(128, 1) fused_rnn_kernel(
    const int*   __restrict__ inputs,
    const float* __restrict__ emb,
    const float* __restrict__ W_ih,
    const float* __restrict__ W_hh,
    const float* __restrict__ b_ih,
    const float* __restrict__ b_hh,
    const float* __restrict__ W_out,
    const float* __restrict__ b_out,
    float*       __restrict__ out)
{
    __shared__ __align__(16) float s_proj[VOCAB * HID];        // 10 KB (pre-scaled)
    __shared__ __align__(16) float s_ring[NROW][RING * HID];   // 2 x 10 KB
    __shared__ int s_idx[NROW][TILE];
    __shared__ volatile int s_prog;            // steps produced (both rows, lockstep)
    __shared__ volatile int s_next[NCONS];     // next tile index per consumer warp

    const int tid  = threadIdx.x;
    const int lane = tid & 31;
    const int wid  = tid >> 5;
    const int b    = blockIdx.x;               // handles rows 2b, 2b+1

    // proj[v][j] = EXSCALE * (b_ih[j]+b_hh[j] + sum_e emb[v][e]*W_ih[j][e])
    for (int i = tid; i < VOCAB * HID; i += 128) {
        int v = i / HID, j = i - v * HID;
        float acc = b_ih[j] + b_hh[j];
#pragma unroll
        for (int e = 0; e < EMB; ++e)
            acc = fmaf(emb[v * EMB + e], W_ih[j * EMB + e], acc);
        s_proj[i] = acc * EXSCALE;
    }
    if (tid == 0) s_prog = 0;
    if (tid < NCONS) s_next[tid] = tid;
    if (tid < HID) {
        s_ring[0][(RING - 1) * HID + tid] = 0.0f;   // h_{-1} = 0
        s_ring[1][(RING - 1) * HID + tid] = 0.0f;
    }
    __syncthreads();

    if (wid == NCONS) {
        // ================= PRODUCER (warp 3): two interleaved recurrences
        const int  j   = lane;
        const bool act = (j < HID);
        const int  jx  = act ? j : 0;

        // W_hh row, pre-scaled by EXSCALE, packed f32x2 (shared by both rows)
        ull w2[10];
        if (act) {
            const float4* wr = (const float4*)(W_hh + j * HID);
#pragma unroll
            for (int q = 0; q < 5; ++q) {
                float4 f = wr[q];
                w2[2*q]   = pk(f.x * EXSCALE, f.y * EXSCALE);
                w2[2*q+1] = pk(f.z * EXSCALE, f.w * EXSCALE);
            }
        } else {
#pragma unroll
            for (int q = 0; q < 10; ++q) w2[q] = 0ull;
        }

        const int* inp0 = inputs + (size_t)(2 * b + 0) * TT;
        const int* inp1 = inputs + (size_t)(2 * b + 1) * TT;

        // prologue: stage chunk-0 indices for both rows, prefetch x_0
        s_idx[0][lane] = inp0[lane];
        s_idx[1][lane] = inp1[lane];
        __syncwarp();
        float x0 = s_proj[s_idx[0][0] * HID + jx];
        float x1 = s_proj[s_idx[1][0] * HID + jx];

        for (int tc = 0; tc < TT; tc += TILE) {
            int ni0 = (tc + TILE < TT) ? inp0[tc + TILE + lane] : 0;
            int ni1 = (tc + TILE < TT) ? inp1[tc + TILE + lane] : 0;

            // back-pressure: both rows' ring slots [tc, tc+32) must be free.
            // All tiles < minNext are complete; row r consumed >= (minNext>>1) tiles.
            int needSteps = tc + TILE - RING;
            if (needSteps > 0) {
                int needTiles = (needSteps + TILE - 1) >> 5;
                if (lane == 0) {
                    for (;;) {
                        int m = s_next[0];
#pragma unroll
                        for (int k = 1; k < NCONS; ++k) m = min(m, s_next[k]);
                        if ((m >> 1) >= needTiles) break;
                        __nanosleep(128);
                    }
                }
                __syncwarp();
            }

#pragma unroll
            for (int tt = 0; tt < TILE; ++tt) {
                const int t    = tc + tt;
                const int rdsl = (t + RING - 1) & (RING - 1);
                const int wrsl = t & (RING - 1);

                // load h_{t-1} for both rows (independent -> overlapped)
                const ulonglong2* ha = (const ulonglong2*)(s_ring[0] + rdsl * HID);
                const ulonglong2* hb = (const ulonglong2*)(s_ring[1] + rdsl * HID);
                ulonglong2 a0 = ha[0], a1 = ha[1], a2 = ha[2], a3 = ha[3], a4 = ha[4];
                ulonglong2 b0 = hb[0], b1 = hb[1], b2 = hb[2], b3 = hb[3], b4 = hb[4];

                // two independent matvecs, 4 FFMA2 chains each
                ull ca0 = pk(x0, 0.0f), ca1 = pk(0.f,0.f), ca2 = pk(0.f,0.f), ca3 = pk(0.f,0.f);
                ull cb0 = pk(x1, 0.0f), cb1 = pk(0.f,0.f), cb2 = pk(0.f,0.f), cb3 = pk(0.f,0.f);
                dfma(ca0, w2[0], a0.x); dfma(cb0, w2[0], b0.x);
                dfma(ca1, w2[1], a0.y); dfma(cb1, w2[1], b0.y);
                dfma(ca2, w2[2], a1.x); dfma(cb2, w2[2], b1.x);
                dfma(ca3, w2[3], a1.y); dfma(cb3, w2[3], b1.y);
                dfma(ca0, w2[4], a2.x); dfma(cb0, w2[4], b2.x);
                dfma(ca1, w2[5], a2.y); dfma(cb1, w2[5], b2.y);
                dfma(ca2, w2[6], a3.x); dfma(cb2, w2[6], b3.x);
                dfma(ca3, w2[7], a3.y); dfma(cb3, w2[7], b3.y);
                dfma(ca0, w2[8], a4.x); dfma(cb0, w2[8], b4.x);
                dfma(ca1, w2[9], a4.y); dfma(cb1, w2[9], b4.y);
                ull da = dadd(dadd(ca0, ca1), dadd(ca2, ca3));
                ull db = dadd(dadd(cb0, cb1), dadd(cb2, cb3));
                float la, hA; upk(la, hA, da);
                float lb, hB; upk(lb, hB, db);

                // prefetch next step's x for both rows (off the chains)
                if (tt < TILE - 1) {
                    x0 = s_proj[s_idx[0][tt + 1] * HID + jx];
                    x1 = s_proj[s_idx[1][tt + 1] * HID + jx];
                }

                float hn0 = tanh_prescaled(la + hA);
                float hn1 = tanh_prescaled(lb + hB);
                if (act) {
                    s_ring[0][wrsl * HID + j] = hn0;
                    s_ring[1][wrsl * HID + j] = hn1;
                }
                // no per-step __syncwarp: same-warp STS->LDS is LSU-ordered
            }

            // publish superstep; stage next chunks' indices
            __syncwarp();
            __threadfence_block();
            if (lane == 0) s_prog = tc + TILE;
            s_idx[0][lane] = ni0;
            s_idx[1][lane] = ni1;
            __syncwarp();
            x0 = s_proj[s_idx[0][0] * HID + jx];
            x1 = s_proj[s_idx[1][0] * HID + jx];
        }
    } else {
        // ============ CONSUMERS (warps 0-2): tiles over {row} x {t-chunk}
        const int v0 = lane * 4;          // 32 lanes x 4 vocab = 128
        ull wo[4][10];
        ull bo[4];
#pragma unroll
        for (int r = 0; r < 4; ++r) {
            const float4* wr = (const float4*)(W_out + (v0 + r) * HID);
#pragma unroll
            for (int q = 0; q < 5; ++q) {
                float4 f = wr[q];
                wo[r][2*q]   = pk(f.x, f.y);
                wo[r][2*q+1] = pk(f.z, f.w);
            }
            bo[r] = pk(b_out[v0 + r], 0.0f);
        }

        for (int tl = wid; tl < NROW * NTILES; tl += NCONS) {
            const int row  = tl & 1;
            const int t0   = (tl >> 1) * TILE;
            const int tend = t0 + TILE;
            if (lane == 0) {
                while (s_prog < tend) __nanosleep(128);
            }
            __syncwarp();
            __threadfence_block();

            const float* ring = s_ring[row];
            float* outp = out + ((size_t)(2 * b + row) * TT + t0) * VOCAB + v0;
#pragma unroll 4
            for (int tt = 0; tt < TILE; ++tt) {
                const ulonglong2* hp = (const ulonglong2*)
                    (ring + ((t0 + tt) & (RING - 1)) * HID);
                ulonglong2 p0 = hp[0], p1 = hp[1], p2 = hp[2], p3 = hp[3], p4 = hp[4];

                float4 res;
#pragma unroll
                for (int r = 0; r < 4; ++r) {
                    ull acc = bo[r];
                    dfma(acc, wo[r][0], p0.x); dfma(acc, wo[r][1], p0.y);
                    dfma(acc, wo[r][2], p1.x); dfma(acc, wo[r][3], p1.y);
                    dfma(acc, wo[r][4], p2.x); dfma(acc, wo[r][5], p2.y);
                    dfma(acc, wo[r][6], p3.x); dfma(acc, wo[r][7], p3.y);
                    dfma(acc, wo[r][8], p4.x); dfma(acc, wo[r][9], p4.y);
                    float lo, hi; upk(lo, hi, acc);
                    (&res.x)[r] = lo + hi;
                }
                *(float4*)(outp + (size_t)tt * VOCAB) = res;   // 512B coalesced
            }
            __syncwarp();
            if (lane == 0) s_next[wid] = tl + NCONS;
        }
    }
}

// ---------------------------------------------------------------------------
// Inputs (metadata order):
// 0: inputs int32 [256,2048]  1: emb [128,10]  2: W_ih [20,10]  3: W_hh [20,20]
// 4: b_ih [20]  5: b_hh [20]  6: W_out [128,20]  7: b_out [128]
// Output: float32 [256,2048,128]
// ---------------------------------------------------------------------------
extern "C" void kernel_launch(void* const* d_in, const int* in_sizes, int n_in,
                              void* d_out, int out_size) {
    const int*   inputs = (const int*)d_in[0];
    const float* emb    = (const float*)d_in[1];
    const float* W_ih   = (const float*)d_in[2];
    const float* W_hh   = (const float*)d_in[3];
    const float* b_ih   = (const float*)d_in[4];
    const float* b_hh   = (const float*)d_in[5];
    const float* W_out  = (const float*)d_in[6];
    const float* b_out  = (const float*)d_in[7];
    float*       out    = (float*)d_out;

    fused_rnn_kernel<<<BB / NROW, 128>>>(inputs, emb, W_ih, W_hh, b_ih, b_hh,
                                         W_out, b_out, out);
}